// round 14
// baseline (speedup 1.0000x reference)
#include <cuda_runtime.h>
#include <cuda_bf16.h>

#define NP 12000
#define NN 100
#define GRID 740          // 148 SMs x 5 resident CTAs
#define RW 12             // padded AoS row: x y z i | xs ys mk pad | pad4 (48B, 16B multiple)

__global__ __launch_bounds__(256, 5)
void pfn_kernel(const float* __restrict__ px, const float* __restrict__ py,
                const float* __restrict__ pz, const float* __restrict__ pi,
                const int*   __restrict__ nv,
                const float* __restrict__ xs, const float* __restrict__ ys,
                const float* __restrict__ mk,
                const float* __restrict__ W,  const float* __restrict__ gamma,
                const float* __restrict__ beta, const float* __restrict__ bnm,
                const float* __restrict__ bnv,
                float* __restrict__ out)
{
    __shared__ __align__(16) float feat[2][NN][RW];
    __shared__ float means[2][3];
    __shared__ float smax[2][8][32];
    __shared__ __align__(16) float gmax[32];

    const int t    = threadIdx.x;
    const int lane = t & 31;
    const int warp = t >> 5;

    // staging role: warp w owns input array w (warp 7 is the gmax-reducer)
    const float* src = 0;
    switch (warp) {
        case 0: src = px; break;
        case 1: src = py; break;
        case 2: src = pz; break;
        case 3: src = pi; break;
        case 4: src = xs; break;
        case 5: src = ys; break;
        case 6: src = mk; break;
        default: break;
    }

    // ---- folded weights: 2 channels per thread ----
    // D = x*(w0+w4+w7) + y*(w1+w5+w8) + z*(w2+w6) + i*w3 - xc*w7 - yc*w8
    //     - (mx*w4 + my*w5 + mz*w6)      [last term = per-pillar constant cp]
    const int pt2 = lane >> 4;        // which of 2 points per warp-iter
    const int ch0 = (lane & 15) * 2;  // first of 2 channels
    const int nb  = warp * 2 + pt2;   // base point index (0..15)
    float W0[2], W1[2], W2[2], W3[2], W7[2], W8[2], w4[2], w5[2], w6[2], b[2];
    #pragma unroll
    for (int j = 0; j < 2; j++) {
        const int u = ch0 + j;
        const float s = rsqrtf(bnv[u] + 1e-3f) * gamma[u];
        b[j] = beta[u] - bnm[u] * s;
        float tw[9];
        #pragma unroll
        for (int c = 0; c < 9; c++) tw[c] = W[u * 9 + c] * s;
        W0[j] = tw[0] + tw[4] + tw[7];
        W1[j] = tw[1] + tw[5] + tw[8];
        W2[j] = tw[2] + tw[6];
        W3[j] = tw[3];
        W7[j] = -tw[7];
        W8[j] = -tw[8];
        w4[j] = tw[4]; w5[j] = tw[5]; w6[j] = tw[6];
    }

    // ---- staging: AoS rows, mean partials via shuffle ----
    auto stage = [&](int pp, int bb) {
        if (src) {
            const int bs = pp * NN;
            float s = 0.f;
            #pragma unroll
            for (int k = 0; k < 4; k++) {
                const int n = lane + 32 * k;
                if (k < 3 || lane < NN - 96) {
                    const float v = __ldcs(src + bs + n);
                    feat[bb][n][warp] = v;
                    if (warp < 3) s += v;
                }
            }
            if (warp < 3) {
                #pragma unroll
                for (int o = 16; o; o >>= 1) s += __shfl_down_sync(0xffffffffu, s, o);
                if (lane == 0) means[bb][warp] = s;
            }
        }
    };

    int p = blockIdx.x;
    int buf = 0;
    stage(p, 0);
    int nvcur = nv[p];
    __syncthreads();   // initial feat[0] ready

    for (; p < NP; p += GRID) {
        const float* f = &feat[buf][nb][0];
        const float inv = 1.0f / (float)nvcur;
        const float mx = means[buf][0] * inv;
        const float my = means[buf][1] * inv;
        const float mz = means[buf][2] * inv;

        // per-pillar constant: cp[j] = -(mx*w4 + my*w5 + mz*w6)
        float cp[2];
        #pragma unroll
        for (int j = 0; j < 2; j++)
            cp[j] = fmaf(-mx, w4[j], fmaf(-my, w5[j], -mz * w6[j]));

        float* const outp = out + (size_t)p * (NN * 64);
        float* const op   = outp + nb * 64 + ch0;

        // ---- main pass: 2 LDS.128 per point, 6 FMA + mask-FMA + max per channel ----
        float vmax0 = -1e30f, vmax1 = -1e30f;
        #pragma unroll
        for (int it = 0; it < 7; it++) {
            if (it < 6 || nb < NN - 96) {
                const float4 a  = *(const float4*)(f + it * (16 * RW));   // x y z i
                const float4 c4 = *(const float4*)(f + it * (16 * RW) + 4); // xc yc m pad
                const float m = c4.z;
                float2 r;
                #pragma unroll
                for (int j = 0; j < 2; j++) {
                    float d = cp[j];
                    d = fmaf(a.x,  W0[j], d);
                    d = fmaf(a.y,  W1[j], d);
                    d = fmaf(a.z,  W2[j], d);
                    d = fmaf(a.w,  W3[j], d);
                    d = fmaf(c4.x, W7[j], d);
                    d = fmaf(c4.y, W8[j], d);
                    const float x = fmaxf(fmaf(m, d, b[j]), 0.0f);
                    if (j == 0) { r.x = x; vmax0 = fmaxf(vmax0, x); }
                    else        { r.y = x; vmax1 = fmaxf(vmax1, x); }
                }
                __stcs((float2*)(op + it * (16 * 64)), r);   // 128B per half-warp
            }
        }

        // ---- channel max partials into smax ----
        vmax0 = fmaxf(vmax0, __shfl_xor_sync(0xffffffffu, vmax0, 16));
        vmax1 = fmaxf(vmax1, __shfl_xor_sync(0xffffffffu, vmax1, 16));
        if (pt2 == 0) {
            smax[buf][warp][ch0]     = vmax0;
            smax[buf][warp][ch0 + 1] = vmax1;
        }
        __syncthreads();   // smax[buf] complete; feat[buf] fully consumed

        // ---- warp 7 reduces gmax while warps 0-6 stage the next pillar ----
        const int pn = p + GRID;
        if (warp == 7) {
            float g = smax[buf][0][lane];
            #pragma unroll
            for (int i = 1; i < 8; i++) g = fmaxf(g, smax[buf][i][lane]);
            gmax[lane] = g;
        } else if (pn < NP) {
            stage(pn, buf ^ 1);
        }
        int nvnext = nvcur;
        if (pn < NP) nvnext = nv[pn];
        __syncthreads();   // gmax ready + feat[buf^1] ready

        // ---- broadcast pass: STG.128, 8-lane groups write 128B rows ----
        {
            const int cg4 = (lane & 7) * 4;   // channel group (4 channels)
            const int pg  = lane >> 3;        // point-in-group (0..3)
            const float4 g4 = *(const float4*)&gmax[cg4];
            float* const bp = outp + (warp * 4 + pg) * 64 + 32 + cg4;
            #pragma unroll
            for (int it = 0; it < 4; it++) {
                if (it < 3 || warp * 4 + pg < NN - 96)
                    __stcs((float4*)(bp + it * (32 * 64)), g4);
            }
        }

        nvcur = nvnext;
        buf ^= 1;
    }
}

extern "C" void kernel_launch(void* const* d_in, const int* in_sizes, int n_in,
                              void* d_out, int out_size)
{
    const float* px = (const float*)d_in[0];
    const float* py = (const float*)d_in[1];
    const float* pz = (const float*)d_in[2];
    const float* pi = (const float*)d_in[3];
    const int*   nv = (const int*)  d_in[4];
    const float* xs = (const float*)d_in[5];
    const float* ys = (const float*)d_in[6];
    const float* mk = (const float*)d_in[7];
    const float* W  = (const float*)d_in[8];
    const float* ga = (const float*)d_in[9];
    const float* be = (const float*)d_in[10];
    const float* bm = (const float*)d_in[11];
    const float* bv = (const float*)d_in[12];
    float* out = (float*)d_out;

    pfn_kernel<<<GRID, 256>>>(px, py, pz, pi, nv, xs, ys, mk, W, ga, be, bm, bv, out);
}